// round 14
// baseline (speedup 1.0000x reference)
#include <cuda_runtime.h>
#include <cuda_bf16.h>
#include <math_constants.h>
#include <cstdint>

#define B_   2
#define S_   4096
#define D_   512
#define H_   8
#define HD_  64
#define MS_  (B_*S_)          // 8192 rows
#define OUT_MAIN (MS_*D_)     // 4194304 floats, then mu(128), logvar(128)

// ---------------- scratch (no allocations allowed) ----------------
__device__ float    g_xm_part[8*1024];
__device__ float    g_lp[B_*D_];
__device__ float    g_xi[MS_*D_];     // x, tf32-rounded (image for QKV projections)
__device__ uint32_t g_wi[4*D_*D_];    // W images: tf32, [nb][k][n^swz]; 0=wv 1=wq 2=wk 3=wo
__device__ uint16_t g_qb[MS_*D_];     // Q bf16, [bh][row][dim], pre-scaled 0.125, +lp
__device__ uint16_t g_kb[MS_*D_];     // K bf16, [bh][row][dim], +lp
__device__ uint16_t g_vt[MS_*D_];     // V bf16, [bh][dim][key]
__device__ float    g_ctx[MS_*D_];    // ctx, tf32-rounded by attn epilogue

// ---------------- helpers ----------------
__device__ __forceinline__ uint32_t f2tf(float f){
    uint32_t u; asm("cvt.rna.tf32.f32 %0, %1;" : "=r"(u) : "f"(f)); return u;
}
__device__ __forceinline__ uint32_t pkbf(float lo, float hi){
    uint32_t d; asm("cvt.rn.bf16x2.f32 %0, %1, %2;" : "=r"(d) : "f"(hi), "f"(lo)); return d;
}
__device__ __forceinline__ void mma_tf32(float* c, const uint32_t* a, uint32_t b0, uint32_t b1){
    asm volatile("mma.sync.aligned.m16n8k8.row.col.f32.tf32.tf32.f32 "
        "{%0,%1,%2,%3}, {%4,%5,%6,%7}, {%8,%9}, {%0,%1,%2,%3};"
        : "+f"(c[0]), "+f"(c[1]), "+f"(c[2]), "+f"(c[3])
        : "r"(a[0]), "r"(a[1]), "r"(a[2]), "r"(a[3]), "r"(b0), "r"(b1));
}
__device__ __forceinline__ void mma_bf16(float* c, uint32_t a0, uint32_t a1, uint32_t a2,
                                         uint32_t a3, uint32_t b0, uint32_t b1){
    asm volatile("mma.sync.aligned.m16n8k16.row.col.f32.bf16.bf16.f32 "
        "{%0,%1,%2,%3}, {%4,%5,%6,%7}, {%8,%9}, {%0,%1,%2,%3};"
        : "+f"(c[0]), "+f"(c[1]), "+f"(c[2]), "+f"(c[3])
        : "r"(a0), "r"(a1), "r"(a2), "r"(a3), "r"(b0), "r"(b1));
}
__device__ __forceinline__ void ldsm4(uint32_t& r0, uint32_t& r1, uint32_t& r2, uint32_t& r3,
                                      uint32_t addr){
    asm volatile("ldmatrix.sync.aligned.m8n8.x4.shared.b16 {%0,%1,%2,%3}, [%4];"
        : "=r"(r0), "=r"(r1), "=r"(r2), "=r"(r3) : "r"(addr));
}
#define CP_ASYNC16(dst, src) \
    asm volatile("cp.async.cg.shared.global [%0], [%1], 16;" :: "r"(dst), "l"(src))
#define CP_COMMIT() asm volatile("cp.async.commit_group;" ::: "memory")
#define CP_WAIT0()  asm volatile("cp.async.wait_group 0;" ::: "memory")

// ---------------- pre-conversion kernels ----------------
__global__ void cvt_x_kernel(const float* __restrict__ x, float* __restrict__ xi)
{
    int idx = (blockIdx.x * 256 + threadIdx.x) * 4;
    float4 v = *(const float4*)(x + idx);
    uint4 u = make_uint4(f2tf(v.x), f2tf(v.y), f2tf(v.z), f2tf(v.w));
    *(uint4*)(xi + idx) = u;
}

// W [gcol][k] row-major -> image [(nb*512 + k)*64 + (n ^ ((k&3)<<3))], nb=gcol>>6, n=gcol&63
__global__ void cvt_w_kernel(const float* __restrict__ W, uint32_t* __restrict__ wi)
{
    int idx4 = blockIdx.x * 256 + threadIdx.x;      // 65536 quads
    int k4 = (idx4 & 127) * 4;
    int gcol = idx4 >> 7;
    int nb = gcol >> 6, n = gcol & 63;
    float4 v = *(const float4*)(W + (size_t)gcol * 512 + k4);
    size_t base = ((size_t)nb * 512 + k4) * 64;
    wi[base          + (n ^ 0 )] = f2tf(v.x);
    wi[base + 64     + (n ^ 8 )] = f2tf(v.y);
    wi[base + 128    + (n ^ 16)] = f2tf(v.z);
    wi[base + 192    + (n ^ 24)] = f2tf(v.w);
}

// ---------------- mean over sequence (partial sums over 8 chunks) ----------------
__global__ void mean_part_kernel(const float* __restrict__ x, float* __restrict__ part)
{
    int gid = blockIdx.x * 256 + threadIdx.x;
    int chunk = blockIdx.y;
    int b = gid >> 9, d = gid & 511;
    const float* p = x + (size_t)b * S_ * D_ + (size_t)chunk * 512 * D_ + d;
    float s = 0.f;
    #pragma unroll 8
    for (int i = 0; i < 512; i++) s += p[(size_t)i * D_];
    part[chunk * 1024 + gid] = s;
}

// ---------------- VAE MLP (single block) ----------------
__global__ void vae_kernel(const float* __restrict__ part, const float* __restrict__ eps,
                           const float* __restrict__ we1, const float* __restrict__ be1,
                           const float* __restrict__ we2, const float* __restrict__ be2,
                           const float* __restrict__ wmu, const float* __restrict__ bmu,
                           const float* __restrict__ wlv, const float* __restrict__ blv,
                           const float* __restrict__ wf,  const float* __restrict__ bf,
                           float* __restrict__ lp, float* __restrict__ out_tail)
{
    __shared__ float s_xm[B_*512];
    __shared__ float s_h1[B_*256];
    __shared__ float s_h2[B_*128];
    __shared__ float s_mu[128], s_lv[128], s_z[128];
    const int t = threadIdx.x;

    for (int i = t; i < 1024; i += 256) {
        float s = 0.f;
        #pragma unroll
        for (int c = 0; c < 8; c++) s += part[c * 1024 + i];
        s_xm[i] = s * (1.0f / (float)S_);
    }
    __syncthreads();
    for (int i = t; i < 512; i += 256) {
        int b = i >> 8, o = i & 255;
        float acc = be1[o];
        const float* w = we1 + (size_t)o * 512;
        const float* xv = s_xm + b * 512;
        #pragma unroll 8
        for (int k2 = 0; k2 < 512; k2++) acc = fmaf(w[k2], xv[k2], acc);
        s_h1[i] = fmaxf(acc, 0.f);
    }
    __syncthreads();
    {
        int b = t >> 7, o = t & 127;
        float acc = be2[o];
        const float* w = we2 + (size_t)o * 256;
        const float* h = s_h1 + b * 256;
        #pragma unroll 8
        for (int k2 = 0; k2 < 256; k2++) acc = fmaf(w[k2], h[k2], acc);
        s_h2[t] = fmaxf(acc, 0.f);
    }
    __syncthreads();
    {
        int which = t >> 7;
        int i = t & 127;
        int b = i >> 6, o = i & 63;
        const float* w = (which ? wlv : wmu) + (size_t)o * 128;
        float acc = which ? blv[o] : bmu[o];
        const float* h = s_h2 + b * 128;
        #pragma unroll 8
        for (int k2 = 0; k2 < 128; k2++) acc = fmaf(w[k2], h[k2], acc);
        if (which) s_lv[i] = acc; else s_mu[i] = acc;
        out_tail[which * 128 + b * 64 + o] = acc;
    }
    __syncthreads();
    if (t < 128) s_z[t] = s_mu[t] + eps[t] * expf(0.5f * s_lv[t]);
    __syncthreads();
    for (int i = t; i < 1024; i += 256) {
        int b = i >> 9, o = i & 511;
        float acc = bf[o];
        const float* w = wf + (size_t)o * 64;
        const float* z = s_z + b * 64;
        #pragma unroll
        for (int k2 = 0; k2 < 64; k2++) acc = fmaf(w[k2], z[k2], acc);
        lp[i] = acc;
    }
}

// ---------------- projection GEMM: tf32 mma + cp.async double buffer ----------------
// X: tf32-rounded fp32 [row][512]. W: pre-swizzled tf32 image. Tile 128x64, k-tiles 64.
// SMEM bytes: X0 @0 (34816) | X1 @34816 | W0 @69632 (16384) | W1 @86016 | total 102400
#define PROJ_SMEM_BYTES 102400

__global__ __launch_bounds__(256, 2) void proj_mma_kernel(
    const float* __restrict__ X, const uint32_t* __restrict__ Wi,
    const float* __restrict__ bias, const float* __restrict__ lp,
    void* __restrict__ out, int mode)
{
    extern __shared__ uint32_t sm[];
    const uint32_t sb = (uint32_t)__cvta_generic_to_shared(sm);

    const int t = threadIdx.x, w = t >> 5, lane = t & 31;
    const int g = lane >> 2, tig = lane & 3;
    const int n0 = blockIdx.x * 64, m0 = blockIdx.y * 128;
    const uint32_t* wsrc = Wi + (size_t)blockIdx.x * 512 * 64;

    float oacc[8][4];
    #pragma unroll
    for (int n = 0; n < 8; n++)
        #pragma unroll
        for (int i = 0; i < 4; i++) oacc[n][i] = 0.f;

    const int rq0 = (w * 16 + g) * 68, rq1 = rq0 + 8 * 68;

    // preload tile 0
    #pragma unroll
    for (int p = 0; p < 8; p++) {
        int idx = p * 256 + t;
        int row = idx >> 4, c4 = idx & 15;
        CP_ASYNC16(sb + row * 272 + c4 * 16, X + (size_t)(m0 + row) * 512 + c4 * 4);
    }
    #pragma unroll
    for (int p = 0; p < 4; p++) {
        int idx = p * 256 + t;
        int kk = idx >> 4, ch = idx & 15;
        CP_ASYNC16(sb + 69632 + kk * 256 + ch * 16, wsrc + (size_t)kk * 64 + ch * 4);
    }
    CP_COMMIT(); CP_WAIT0();
    __syncthreads();

    for (int kt = 0; kt < 8; kt++) {
        const int cur = kt & 1;
        uint32_t* sX = sm + cur * 8704;
        uint32_t* sW = sm + 17408 + cur * 4096;

        // async prefetch next k-tile
        if (kt < 7) {
            const int k0 = (kt + 1) * 64;
            const uint32_t xd = sb + (cur ^ 1) * 34816;
            const uint32_t wd = sb + 69632 + (cur ^ 1) * 16384;
            #pragma unroll
            for (int p = 0; p < 8; p++) {
                int idx = p * 256 + t;
                int row = idx >> 4, c4 = idx & 15;
                CP_ASYNC16(xd + row * 272 + c4 * 16,
                           X + (size_t)(m0 + row) * 512 + k0 + c4 * 4);
            }
            #pragma unroll
            for (int p = 0; p < 4; p++) {
                int idx = p * 256 + t;
                int kk = idx >> 4, ch = idx & 15;
                CP_ASYNC16(wd + kk * 256 + ch * 16,
                           wsrc + (size_t)(k0 + kk) * 64 + ch * 4);
            }
            CP_COMMIT();
        }

        #pragma unroll
        for (int ks = 0; ks < 8; ks++) {
            uint32_t a[4];
            a[0] = sX[rq0 + ks * 8 + tig];
            a[1] = sX[rq1 + ks * 8 + tig];
            a[2] = sX[rq0 + ks * 8 + tig + 4];
            a[3] = sX[rq1 + ks * 8 + tig + 4];
            #pragma unroll
            for (int nt = 0; nt < 8; nt++) {
                uint32_t b0 = sW[(ks * 8 + tig    ) * 64 + ((nt * 8 + g) ^ (tig << 3))];
                uint32_t b1 = sW[(ks * 8 + tig + 4) * 64 + ((nt * 8 + g) ^ (tig << 3))];
                mma_tf32(oacc[nt], a, b0, b1);
            }
        }

        if (kt < 7) CP_WAIT0();
        __syncthreads();
    }

    const int bidx = m0 >> 12;
    const int s0 = (m0 & 4095) + w * 16 + g;

    if (mode == 0) {
        float* op = (float*)out + (size_t)(m0 + w * 16) * 512 + n0;
        #pragma unroll
        for (int nt = 0; nt < 8; nt++) {
            int col = nt * 8 + 2 * tig;
            float b0 = bias[n0 + col], b1 = bias[n0 + col + 1];
            *(float2*)(op + (size_t)g       * 512 + col) =
                make_float2(oacc[nt][0] + b0, oacc[nt][1] + b1);
            *(float2*)(op + (size_t)(g + 8) * 512 + col) =
                make_float2(oacc[nt][2] + b0, oacc[nt][3] + b1);
        }
    } else if (mode == 3) {               // V transposed bf16 [bh][dim][key]
        __nv_bfloat16* ov = (__nv_bfloat16*)out;
        #pragma unroll
        for (int nt = 0; nt < 8; nt++) {
            int col = n0 + nt * 8 + 2 * tig;
            int h = col >> 6, d = col & 63;
            float b0 = bias[col], b1 = bias[col + 1];
            size_t a0 = ((size_t)(bidx * 8 + h) * 64 + d) * 4096;
            size_t a1 = a0 + 4096;
            ov[a0 + s0    ] = __float2bfloat16(oacc[nt][0] + b0);
            ov[a1 + s0    ] = __float2bfloat16(oacc[nt][1] + b1);
            ov[a0 + s0 + 8] = __float2bfloat16(oacc[nt][2] + b0);
            ov[a1 + s0 + 8] = __float2bfloat16(oacc[nt][3] + b1);
        }
    } else {                              // Q/K bf16 [bh][row][dim] (+lp, Q scaled)
        uint32_t* oq = (uint32_t*)out;
        const float sc = (mode == 1) ? 0.125f : 1.0f;
        #pragma unroll
        for (int nt = 0; nt < 8; nt++) {
            int col = n0 + nt * 8 + 2 * tig;
            int h = col >> 6, dh = (col & 63) >> 1;
            float b0 = bias[col] + lp[bidx * 512 + col];
            float b1 = bias[col + 1] + lp[bidx * 512 + col + 1];
            size_t rbase = (size_t)(bidx * 8 + h) * 4096;
            oq[(rbase + s0    ) * 32 + dh] =
                pkbf((oacc[nt][0] + b0) * sc, (oacc[nt][1] + b1) * sc);
            oq[(rbase + s0 + 8) * 32 + dh] =
                pkbf((oacc[nt][2] + b0) * sc, (oacc[nt][3] + b1) * sc);
        }
    }
}

// ---------------- flash attention: 64 q-rows/CTA, 4 CTAs/SM, cp.async double buffer ----------------
// CTA: 128 thr (4 warps), 64 q-rows, key tiles 64. Warp w: rows w*16+g, +8.
// SMEM bytes: kbuf0 0 | kbuf1 9216 | vbuf0 18432 | vbuf1 27648 | qbuf 36864..46080
#define KB0 0
#define VB0 18432
#define QB0 36864
#define ATT_SMEM_BYTES 46080

__global__ __launch_bounds__(128, 4) void attn_mma_kernel(
    const uint16_t* __restrict__ Qb, const uint16_t* __restrict__ Kb,
    const uint16_t* __restrict__ Vt, float* __restrict__ Oc)
{
    extern __shared__ uint32_t sm[];
    const uint32_t sb = (uint32_t)__cvta_generic_to_shared(sm);

    const int t = threadIdx.x, w = t >> 5, lane = t & 31;
    const int g = lane >> 2, tig = lane & 3;
    const int l7 = lane & 7, lh = (lane >> 3) & 1, lq = lane >> 4;
    const int bh = blockIdx.y, qt = blockIdx.x;

    // Q tile: 64 rows x 8 chunks (512 chunks / 128 thr = 4 per thread)
    {
        const uint16_t* qsrc = Qb + ((size_t)bh * 4096 + qt * 64) * 64;
        #pragma unroll
        for (int p = 0; p < 4; p++) {
            int idx = p * 128 + t;
            int row = idx >> 3, c = idx & 7;
            CP_ASYNC16(sb + QB0 + row * 144 + c * 16,
                       qsrc + (size_t)row * 64 + c * 8);
        }
    }
    // K/V tile 0 (64 rows x 8 chunks each)
    {
        const uint16_t* ksrc = Kb + (size_t)bh * 4096 * 64;
        const uint16_t* vsrc = Vt + (size_t)bh * 64 * 4096;
        #pragma unroll
        for (int p = 0; p < 4; p++) {
            int idx = p * 128 + t;
            int row = idx >> 3, c = idx & 7;
            CP_ASYNC16(sb + KB0 + row * 144 + c * 16,
                       ksrc + (size_t)row * 64 + c * 8);
            CP_ASYNC16(sb + VB0 + row * 144 + ((c ^ (row >> 3)) * 16),
                       vsrc + (size_t)row * 4096 + c * 8);
        }
    }
    CP_COMMIT();

    const uint32_t aQ = sb + QB0 + ((w * 16 + lh * 8 + l7) * 144) + lq * 16;
    uint32_t kRow[4], vRow[4];
    #pragma unroll
    for (int ntp = 0; ntp < 4; ntp++) {
        kRow[ntp] = (uint32_t)(((2 * ntp + lq) * 8 + l7) * 144 + lh * 16);
        vRow[ntp] = (uint32_t)(((2 * ntp + lq) * 8 + l7) * 144);
    }

    float oacc[8][4];
    #pragma unroll
    for (int n = 0; n < 8; n++)
        #pragma unroll
        for (int i = 0; i < 4; i++) oacc[n][i] = 0.f;
    float lsum0 = 0.f, lsum1 = 0.f;

    CP_WAIT0();
    __syncthreads();

    for (int kt = 0; kt < 64; kt++) {
        const int cur = kt & 1;
        const uint32_t kbase = sb + KB0 + cur * 9216;
        const uint32_t vbase = sb + VB0 + cur * 9216;

        if (kt < 63) {
            const uint16_t* ksrc = Kb + ((size_t)bh * 4096 + (kt + 1) * 64) * 64;
            const uint16_t* vsrc = Vt + (size_t)bh * 64 * 4096 + (kt + 1) * 64;
            const uint32_t kd = sb + KB0 + (cur ^ 1) * 9216;
            const uint32_t vd = sb + VB0 + (cur ^ 1) * 9216;
            #pragma unroll
            for (int p = 0; p < 4; p++) {
                int idx = p * 128 + t;
                int row = idx >> 3, c = idx & 7;
                CP_ASYNC16(kd + row * 144 + c * 16, ksrc + (size_t)row * 64 + c * 8);
                CP_ASYNC16(vd + row * 144 + ((c ^ (row >> 3)) * 16),
                           vsrc + (size_t)row * 4096 + c * 8);
            }
            CP_COMMIT();
        }

        // MMA1
        float sacc[8][4];
        #pragma unroll
        for (int n = 0; n < 8; n++)
            #pragma unroll
            for (int i = 0; i < 4; i++) sacc[n][i] = 0.f;
        #pragma unroll
        for (int ks = 0; ks < 4; ks++) {
            uint32_t a0, a1, a2, a3;
            ldsm4(a0, a1, a2, a3, aQ + ks * 32);
            #pragma unroll
            for (int ntp = 0; ntp < 4; ntp++) {
                uint32_t b0, b1, b2, b3;
                ldsm4(b0, b1, b2, b3, kbase + kRow[ntp] + ks * 32);
                mma_bf16(sacc[2 * ntp    ], a0, a1, a2, a3, b0, b1);
                mma_bf16(sacc[2 * ntp + 1], a0, a1, a2, a3, b2, b3);
            }
        }

        // softmax in registers
        #pragma unroll
        for (int nt = 0; nt < 8; nt++) {
            float e0 = __expf(sacc[nt][0]);
            float e1 = __expf(sacc[nt][1]);
            float e2 = __expf(sacc[nt][2]);
            float e3 = __expf(sacc[nt][3]);
            lsum0 += e0 + e1;
            lsum1 += e2 + e3;
            sacc[nt][0] = e0; sacc[nt][1] = e1; sacc[nt][2] = e2; sacc[nt][3] = e3;
        }

        // MMA2
        #pragma unroll
        for (int ks = 0; ks < 4; ks++) {
            uint32_t a0 = pkbf(sacc[2*ks    ][0], sacc[2*ks    ][1]);
            uint32_t a1 = pkbf(sacc[2*ks    ][2], sacc[2*ks    ][3]);
            uint32_t a2 = pkbf(sacc[2*ks + 1][0], sacc[2*ks + 1][1]);
            uint32_t a3 = pkbf(sacc[2*ks + 1][2], sacc[2*ks + 1][3]);
            #pragma unroll
            for (int ntp = 0; ntp < 4; ntp++) {
                uint32_t xr = (uint32_t)(((2 * ks + lh) ^ (2 * ntp + lq)) << 4);
                uint32_t b0, b1, b2, b3;
                ldsm4(b0, b1, b2, b3, vbase + vRow[ntp] + xr);
                mma_bf16(oacc[2 * ntp    ], a0, a1, a2, a3, b0, b1);
                mma_bf16(oacc[2 * ntp + 1], a0, a1, a2, a3, b2, b3);
            }
        }

        if (kt < 63) CP_WAIT0();
        __syncthreads();
    }

    // epilogue: normalize + tf32-round ctx
    lsum0 += __shfl_xor_sync(0xffffffffu, lsum0, 1);
    lsum0 += __shfl_xor_sync(0xffffffffu, lsum0, 2);
    lsum1 += __shfl_xor_sync(0xffffffffu, lsum1, 1);
    lsum1 += __shfl_xor_sync(0xffffffffu, lsum1, 2);
    float inv0 = 1.0f / lsum0, inv1 = 1.0f / lsum1;

    const size_t obase = (size_t)(bh >> 3) * S_ * D_ + (size_t)(bh & 7) * HD_;
    uint32_t* op = (uint32_t*)(Oc + obase + (size_t)(qt * 64 + w * 16) * D_);
    #pragma unroll
    for (int nt = 0; nt < 8; nt++) {
        int col = nt * 8 + 2 * tig;
        *(uint2*)(op + (size_t)g       * D_ + col) =
            make_uint2(f2tf(oacc[nt][0] * inv0), f2tf(oacc[nt][1] * inv0));
        *(uint2*)(op + (size_t)(g + 8) * D_ + col) =
            make_uint2(f2tf(oacc[nt][2] * inv1), f2tf(oacc[nt][3] * inv1));
    }
}

// ---------------- launch ----------------
extern "C" void kernel_launch(void* const* d_in, const int* in_sizes, int n_in,
                              void* d_out, int out_size)
{
    (void)in_sizes; (void)n_in; (void)out_size;
    const float* x   = (const float*)d_in[0];
    const float* eps = (const float*)d_in[1];
    const float* wq  = (const float*)d_in[2];
    const float* bq  = (const float*)d_in[3];
    const float* wk  = (const float*)d_in[4];
    const float* bk  = (const float*)d_in[5];
    const float* wv  = (const float*)d_in[6];
    const float* bv  = (const float*)d_in[7];
    const float* wo  = (const float*)d_in[8];
    const float* bo  = (const float*)d_in[9];
    const float* we1 = (const float*)d_in[10];
    const float* be1 = (const float*)d_in[11];
    const float* we2 = (const float*)d_in[12];
    const float* be2 = (const float*)d_in[13];
    const float* wmu = (const float*)d_in[14];
    const float* bmu = (const float*)d_in[15];
    const float* wlv = (const float*)d_in[16];
    const float* blv = (const float*)d_in[17];
    const float* wf  = (const float*)d_in[18];
    const float* bf  = (const float*)d_in[19];
    float* out = (float*)d_out;

    float *p_xm, *p_lp, *p_xi, *p_ctx;
    uint32_t *p_wi;
    uint16_t *p_qb, *p_kb, *p_vt;
    cudaGetSymbolAddress((void**)&p_xm,  g_xm_part);
    cudaGetSymbolAddress((void**)&p_lp,  g_lp);
    cudaGetSymbolAddress((void**)&p_xi,  g_xi);
    cudaGetSymbolAddress((void**)&p_wi,  g_wi);
    cudaGetSymbolAddress((void**)&p_qb,  g_qb);
    cudaGetSymbolAddress((void**)&p_kb,  g_kb);
    cudaGetSymbolAddress((void**)&p_vt,  g_vt);
    cudaGetSymbolAddress((void**)&p_ctx, g_ctx);

    cudaFuncSetAttribute(attn_mma_kernel,
                         cudaFuncAttributeMaxDynamicSharedMemorySize, ATT_SMEM_BYTES);
    cudaFuncSetAttribute(proj_mma_kernel,
                         cudaFuncAttributeMaxDynamicSharedMemorySize, PROJ_SMEM_BYTES);

    // pre-conversion passes
    cvt_x_kernel<<<MS_*D_/1024, 256>>>(x, p_xi);
    cvt_w_kernel<<<256, 256>>>(wv, p_wi);
    cvt_w_kernel<<<256, 256>>>(wq, p_wi + 1*D_*D_);
    cvt_w_kernel<<<256, 256>>>(wk, p_wi + 2*D_*D_);
    cvt_w_kernel<<<256, 256>>>(wo, p_wi + 3*D_*D_);

    mean_part_kernel<<<dim3(4, 8), 256>>>(x, p_xm);
    vae_kernel<<<1, 256>>>(p_xm, eps, we1, be1, we2, be2, wmu, bmu,
                           wlv, blv, wf, bf, p_lp, out + OUT_MAIN);

    dim3 pgrid(8, 64);
    proj_mma_kernel<<<pgrid, 256, PROJ_SMEM_BYTES>>>(p_xi, p_wi,           bv, p_lp, p_vt, 3);
    proj_mma_kernel<<<pgrid, 256, PROJ_SMEM_BYTES>>>(p_xi, p_wi + 1*D_*D_, bq, p_lp, p_qb, 1);
    proj_mma_kernel<<<pgrid, 256, PROJ_SMEM_BYTES>>>(p_xi, p_wi + 2*D_*D_, bk, p_lp, p_kb, 2);

    attn_mma_kernel<<<dim3(64, 16), 128, ATT_SMEM_BYTES>>>(p_qb, p_kb, p_vt, p_ctx);

    proj_mma_kernel<<<pgrid, 256, PROJ_SMEM_BYTES>>>(p_ctx, p_wi + 3*D_*D_, bo, p_lp, out, 0);
}

// round 16
// speedup vs baseline: 1.0489x; 1.0489x over previous
#include <cuda_runtime.h>
#include <cuda_bf16.h>
#include <math_constants.h>
#include <cstdint>

#define B_   2
#define S_   4096
#define D_   512
#define H_   8
#define HD_  64
#define MS_  (B_*S_)          // 8192 rows
#define OUT_MAIN (MS_*D_)     // 4194304 floats, then mu(128), logvar(128)

// ---------------- scratch (no allocations allowed) ----------------
__device__ float    g_xm_part[8*1024];
__device__ float    g_lp[B_*D_];
__device__ float    g_xi[MS_*D_];     // x, tf32-rounded
__device__ float    g_wi[4*D_*D_];    // W tf32-rounded, original [gcol][k] layout; 0=wv 1=wq 2=wk 3=wo
__device__ uint16_t g_qb[MS_*D_];     // Q bf16, [bh][row][dim], pre-scaled 0.125, +lp
__device__ uint16_t g_kb[MS_*D_];     // K bf16, [bh][row][dim], +lp
__device__ uint16_t g_vt[MS_*D_];     // V bf16, [bh][dim][key]
__device__ float    g_ctx[MS_*D_];    // ctx, tf32-rounded by attn epilogue

// ---------------- helpers ----------------
__device__ __forceinline__ uint32_t f2tf(float f){
    uint32_t u; asm("cvt.rna.tf32.f32 %0, %1;" : "=r"(u) : "f"(f)); return u;
}
__device__ __forceinline__ uint32_t pkbf(float lo, float hi){
    uint32_t d; asm("cvt.rn.bf16x2.f32 %0, %1, %2;" : "=r"(d) : "f"(hi), "f"(lo)); return d;
}
__device__ __forceinline__ void mma_tf32(float* c, const uint32_t* a, uint32_t b0, uint32_t b1){
    asm volatile("mma.sync.aligned.m16n8k8.row.col.f32.tf32.tf32.f32 "
        "{%0,%1,%2,%3}, {%4,%5,%6,%7}, {%8,%9}, {%0,%1,%2,%3};"
        : "+f"(c[0]), "+f"(c[1]), "+f"(c[2]), "+f"(c[3])
        : "r"(a[0]), "r"(a[1]), "r"(a[2]), "r"(a[3]), "r"(b0), "r"(b1));
}
__device__ __forceinline__ void mma_bf16(float* c, uint32_t a0, uint32_t a1, uint32_t a2,
                                         uint32_t a3, uint32_t b0, uint32_t b1){
    asm volatile("mma.sync.aligned.m16n8k16.row.col.f32.bf16.bf16.f32 "
        "{%0,%1,%2,%3}, {%4,%5,%6,%7}, {%8,%9}, {%0,%1,%2,%3};"
        : "+f"(c[0]), "+f"(c[1]), "+f"(c[2]), "+f"(c[3])
        : "r"(a0), "r"(a1), "r"(a2), "r"(a3), "r"(b0), "r"(b1));
}
__device__ __forceinline__ void ldsm4(uint32_t& r0, uint32_t& r1, uint32_t& r2, uint32_t& r3,
                                      uint32_t addr){
    asm volatile("ldmatrix.sync.aligned.m8n8.x4.shared.b16 {%0,%1,%2,%3}, [%4];"
        : "=r"(r0), "=r"(r1), "=r"(r2), "=r"(r3) : "r"(addr));
}
#define CP_ASYNC16(dst, src) \
    asm volatile("cp.async.cg.shared.global [%0], [%1], 16;" :: "r"(dst), "l"(src))
#define CP_COMMIT() asm volatile("cp.async.commit_group;" ::: "memory")
#define CP_WAIT0()  asm volatile("cp.async.wait_group 0;" ::: "memory")

// ---------------- fused tf32-rounding pre-pass (x + 4 W's in one launch) ----------------
__global__ void cvt_all_kernel(const float* __restrict__ x,
                               const float* __restrict__ wv, const float* __restrict__ wq,
                               const float* __restrict__ wk, const float* __restrict__ wo,
                               float* __restrict__ xi, float* __restrict__ wi)
{
    int b = blockIdx.x;
    const float* src; float* dst; int off;
    if (b < 4096) { src = x; dst = xi; off = b; }
    else {
        int r = b - 4096;
        int wsel = r >> 8;                 // 256 blocks per W (512*512/1024)
        off = r & 255;
        src = (wsel == 0) ? wv : (wsel == 1) ? wq : (wsel == 2) ? wk : wo;
        dst = wi + (size_t)wsel * D_ * D_;
    }
    int idx = (off * 256 + threadIdx.x) * 4;
    float4 v = *(const float4*)(src + idx);
    uint4 u = make_uint4(f2tf(v.x), f2tf(v.y), f2tf(v.z), f2tf(v.w));
    *(uint4*)(dst + idx) = u;
}

// ---------------- mean over sequence (partial sums over 8 chunks) ----------------
__global__ void mean_part_kernel(const float* __restrict__ x, float* __restrict__ part)
{
    int gid = blockIdx.x * 256 + threadIdx.x;
    int chunk = blockIdx.y;
    int b = gid >> 9, d = gid & 511;
    const float* p = x + (size_t)b * S_ * D_ + (size_t)chunk * 512 * D_ + d;
    float s = 0.f;
    #pragma unroll 8
    for (int i = 0; i < 512; i++) s += p[(size_t)i * D_];
    part[chunk * 1024 + gid] = s;
}

// ---------------- VAE MLP (single block) ----------------
__global__ void vae_kernel(const float* __restrict__ part, const float* __restrict__ eps,
                           const float* __restrict__ we1, const float* __restrict__ be1,
                           const float* __restrict__ we2, const float* __restrict__ be2,
                           const float* __restrict__ wmu, const float* __restrict__ bmu,
                           const float* __restrict__ wlv, const float* __restrict__ blv,
                           const float* __restrict__ wf,  const float* __restrict__ bf,
                           float* __restrict__ lp, float* __restrict__ out_tail)
{
    __shared__ float s_xm[B_*512];
    __shared__ float s_h1[B_*256];
    __shared__ float s_h2[B_*128];
    __shared__ float s_mu[128], s_lv[128], s_z[128];
    const int t = threadIdx.x;

    for (int i = t; i < 1024; i += 256) {
        float s = 0.f;
        #pragma unroll
        for (int c = 0; c < 8; c++) s += part[c * 1024 + i];
        s_xm[i] = s * (1.0f / (float)S_);
    }
    __syncthreads();
    for (int i = t; i < 512; i += 256) {
        int b = i >> 8, o = i & 255;
        float acc = be1[o];
        const float* w = we1 + (size_t)o * 512;
        const float* xv = s_xm + b * 512;
        #pragma unroll 8
        for (int k2 = 0; k2 < 512; k2++) acc = fmaf(w[k2], xv[k2], acc);
        s_h1[i] = fmaxf(acc, 0.f);
    }
    __syncthreads();
    {
        int b = t >> 7, o = t & 127;
        float acc = be2[o];
        const float* w = we2 + (size_t)o * 256;
        const float* h = s_h1 + b * 256;
        #pragma unroll 8
        for (int k2 = 0; k2 < 256; k2++) acc = fmaf(w[k2], h[k2], acc);
        s_h2[t] = fmaxf(acc, 0.f);
    }
    __syncthreads();
    {
        int which = t >> 7;
        int i = t & 127;
        int b = i >> 6, o = i & 63;
        const float* w = (which ? wlv : wmu) + (size_t)o * 128;
        float acc = which ? blv[o] : bmu[o];
        const float* h = s_h2 + b * 128;
        #pragma unroll 8
        for (int k2 = 0; k2 < 128; k2++) acc = fmaf(w[k2], h[k2], acc);
        if (which) s_lv[i] = acc; else s_mu[i] = acc;
        out_tail[which * 128 + b * 64 + o] = acc;
    }
    __syncthreads();
    if (t < 128) s_z[t] = s_mu[t] + eps[t] * expf(0.5f * s_lv[t]);
    __syncthreads();
    for (int i = t; i < 1024; i += 256) {
        int b = i >> 9, o = i & 511;
        float acc = bf[o];
        const float* w = wf + (size_t)o * 64;
        const float* z = s_z + b * 64;
        #pragma unroll
        for (int k2 = 0; k2 < 64; k2++) acc = fmaf(w[k2], z[k2], acc);
        lp[i] = acc;
    }
}

// ---------------- projection GEMM: tf32 mma + ldmatrix + cp.async double buffer ----------------
// X: tf32 fp32 [row][512], SMEM rows 272B (64 words + pad). W: tf32 fp32 [gcol][512] (n-major).
// Per k-tile: X = 128 rows x 16 chunks of 16B, W = 64 rows x 16 chunks.
// SMEM bytes: X0 @0 (34816) | X1 @34816 | W0 @69632 (17408) | W1 @87040 | total 104448
#define PROJ_SMEM_BYTES 104448

__global__ __launch_bounds__(256, 2) void proj_mma_kernel(
    const float* __restrict__ X, const float* __restrict__ Wi,
    const float* __restrict__ bias, const float* __restrict__ lp,
    void* __restrict__ out, int mode)
{
    extern __shared__ uint32_t sm[];
    const uint32_t sb = (uint32_t)__cvta_generic_to_shared(sm);

    const int t = threadIdx.x, w = t >> 5, lane = t & 31;
    const int g = lane >> 2, tig = lane & 3;
    const int n0 = blockIdx.x * 64, m0 = blockIdx.y * 128;
    const float* wsrc = Wi + (size_t)n0 * 512;

    float oacc[8][4];
    #pragma unroll
    for (int n = 0; n < 8; n++)
        #pragma unroll
        for (int i = 0; i < 4; i++) oacc[n][i] = 0.f;

    // ldmatrix per-lane byte offsets (row stride 272B)
    const uint32_t aXoff = (uint32_t)((w * 16 + (lane & 7) + ((lane >> 3) & 1) * 8) * 272
                                      + (lane >> 4) * 16);
    uint32_t wRow[4];
    #pragma unroll
    for (int ntp = 0; ntp < 4; ntp++)
        wRow[ntp] = (uint32_t)((16 * ntp + (lane & 7) + ((lane >> 4) << 3)) * 272
                               + ((lane >> 3) & 1) * 16);

    // preload tile 0: X 2048 chunks (8/thr), W 1024 chunks (4/thr)
    #pragma unroll
    for (int p = 0; p < 8; p++) {
        int idx = p * 256 + t;
        int row = idx >> 4, c = idx & 15;
        CP_ASYNC16(sb + row * 272 + c * 16, X + (size_t)(m0 + row) * 512 + c * 4);
    }
    #pragma unroll
    for (int p = 0; p < 4; p++) {
        int idx = p * 256 + t;
        int row = idx >> 4, c = idx & 15;
        CP_ASYNC16(sb + 69632 + row * 272 + c * 16, wsrc + (size_t)row * 512 + c * 4);
    }
    CP_COMMIT(); CP_WAIT0();
    __syncthreads();

    for (int kt = 0; kt < 8; kt++) {
        const int cur = kt & 1;
        const uint32_t xbase = sb + cur * 34816;
        const uint32_t wbase = sb + 69632 + cur * 17408;

        // async prefetch next k-tile
        if (kt < 7) {
            const int k0 = (kt + 1) * 64;
            const uint32_t xd = sb + (cur ^ 1) * 34816;
            const uint32_t wd = sb + 69632 + (cur ^ 1) * 17408;
            #pragma unroll
            for (int p = 0; p < 8; p++) {
                int idx = p * 256 + t;
                int row = idx >> 4, c = idx & 15;
                CP_ASYNC16(xd + row * 272 + c * 16,
                           X + (size_t)(m0 + row) * 512 + k0 + c * 4);
            }
            #pragma unroll
            for (int p = 0; p < 4; p++) {
                int idx = p * 256 + t;
                int row = idx >> 4, c = idx & 15;
                CP_ASYNC16(wd + row * 272 + c * 16,
                           wsrc + (size_t)row * 512 + k0 + c * 4);
            }
            CP_COMMIT();
        }

        #pragma unroll
        for (int ks = 0; ks < 8; ks++) {
            uint32_t a[4];
            ldsm4(a[0], a[1], a[2], a[3], xbase + aXoff + ks * 32);
            #pragma unroll
            for (int ntp = 0; ntp < 4; ntp++) {
                uint32_t b0, b1, b2, b3;
                ldsm4(b0, b1, b2, b3, wbase + wRow[ntp] + ks * 32);
                mma_tf32(oacc[2 * ntp    ], a, b0, b1);
                mma_tf32(oacc[2 * ntp + 1], a, b2, b3);
            }
        }

        if (kt < 7) CP_WAIT0();
        __syncthreads();
    }

    const int bidx = m0 >> 12;
    const int s0 = (m0 & 4095) + w * 16 + g;

    if (mode == 0) {
        float* op = (float*)out + (size_t)(m0 + w * 16) * 512 + n0;
        #pragma unroll
        for (int nt = 0; nt < 8; nt++) {
            int col = nt * 8 + 2 * tig;
            float b0 = bias[n0 + col], b1 = bias[n0 + col + 1];
            *(float2*)(op + (size_t)g       * 512 + col) =
                make_float2(oacc[nt][0] + b0, oacc[nt][1] + b1);
            *(float2*)(op + (size_t)(g + 8) * 512 + col) =
                make_float2(oacc[nt][2] + b0, oacc[nt][3] + b1);
        }
    } else if (mode == 3) {               // V transposed bf16 [bh][dim][key]
        __nv_bfloat16* ov = (__nv_bfloat16*)out;
        #pragma unroll
        for (int nt = 0; nt < 8; nt++) {
            int col = n0 + nt * 8 + 2 * tig;
            int h = col >> 6, d = col & 63;
            float b0 = bias[col], b1 = bias[col + 1];
            size_t a0 = ((size_t)(bidx * 8 + h) * 64 + d) * 4096;
            size_t a1 = a0 + 4096;
            ov[a0 + s0    ] = __float2bfloat16(oacc[nt][0] + b0);
            ov[a1 + s0    ] = __float2bfloat16(oacc[nt][1] + b1);
            ov[a0 + s0 + 8] = __float2bfloat16(oacc[nt][2] + b0);
            ov[a1 + s0 + 8] = __float2bfloat16(oacc[nt][3] + b1);
        }
    } else {                              // Q/K bf16 [bh][row][dim] (+lp, Q scaled)
        uint32_t* oq = (uint32_t*)out;
        const float sc = (mode == 1) ? 0.125f : 1.0f;
        #pragma unroll
        for (int nt = 0; nt < 8; nt++) {
            int col = n0 + nt * 8 + 2 * tig;
            int h = col >> 6, dh = (col & 63) >> 1;
            float b0 = bias[col] + lp[bidx * 512 + col];
            float b1 = bias[col + 1] + lp[bidx * 512 + col + 1];
            size_t rbase = (size_t)(bidx * 8 + h) * 4096;
            oq[(rbase + s0    ) * 32 + dh] =
                pkbf((oacc[nt][0] + b0) * sc, (oacc[nt][1] + b1) * sc);
            oq[(rbase + s0 + 8) * 32 + dh] =
                pkbf((oacc[nt][2] + b0) * sc, (oacc[nt][3] + b1) * sc);
        }
    }
}

// ---------------- flash attention (R13 config): bf16 + ldmatrix + cp.async double buffer ----------------
#define KB0 0
#define VB0 18432
#define QB0 36864
#define ATT_SMEM_BYTES 55296

__global__ __launch_bounds__(256, 2) void attn_mma_kernel(
    const uint16_t* __restrict__ Qb, const uint16_t* __restrict__ Kb,
    const uint16_t* __restrict__ Vt, float* __restrict__ Oc)
{
    extern __shared__ uint32_t sm[];
    const uint32_t sb = (uint32_t)__cvta_generic_to_shared(sm);

    const int t = threadIdx.x, w = t >> 5, lane = t & 31;
    const int g = lane >> 2, tig = lane & 3;
    const int l7 = lane & 7, lh = (lane >> 3) & 1, lq = lane >> 4;
    const int bh = blockIdx.y, qt = blockIdx.x;

    // Q tile
    {
        const uint16_t* qsrc = Qb + ((size_t)bh * 4096 + qt * 128) * 64;
        #pragma unroll
        for (int p = 0; p < 4; p++) {
            int idx = p * 256 + t;
            int row = idx >> 3, c = idx & 7;
            CP_ASYNC16(sb + QB0 + row * 144 + c * 16,
                       qsrc + (size_t)row * 64 + c * 8);
        }
    }
    // K/V tile 0
    {
        const uint16_t* ksrc = Kb + (size_t)bh * 4096 * 64;
        const uint16_t* vsrc = Vt + (size_t)bh * 64 * 4096;
        #pragma unroll
        for (int p = 0; p < 2; p++) {
            int idx = p * 256 + t;
            int row = idx >> 3, c = idx & 7;
            CP_ASYNC16(sb + KB0 + row * 144 + c * 16,
                       ksrc + (size_t)row * 64 + c * 8);
            CP_ASYNC16(sb + VB0 + row * 144 + ((c ^ (row >> 3)) * 16),
                       vsrc + (size_t)row * 4096 + c * 8);
        }
    }
    CP_COMMIT();

    const uint32_t aQ = sb + QB0 + ((w * 16 + lh * 8 + l7) * 144) + lq * 16;
    uint32_t kRow[4], vRow[4];
    #pragma unroll
    for (int ntp = 0; ntp < 4; ntp++) {
        kRow[ntp] = (uint32_t)(((2 * ntp + lq) * 8 + l7) * 144 + lh * 16);
        vRow[ntp] = (uint32_t)(((2 * ntp + lq) * 8 + l7) * 144);
    }

    float oacc[8][4];
    #pragma unroll
    for (int n = 0; n < 8; n++)
        #pragma unroll
        for (int i = 0; i < 4; i++) oacc[n][i] = 0.f;
    float lsum0 = 0.f, lsum1 = 0.f;

    CP_WAIT0();
    __syncthreads();

    for (int kt = 0; kt < 64; kt++) {
        const int cur = kt & 1;
        const uint32_t kbase = sb + KB0 + cur * 9216;
        const uint32_t vbase = sb + VB0 + cur * 9216;

        if (kt < 63) {
            const uint16_t* ksrc = Kb + ((size_t)bh * 4096 + (kt + 1) * 64) * 64;
            const uint16_t* vsrc = Vt + (size_t)bh * 64 * 4096 + (kt + 1) * 64;
            const uint32_t kd = sb + KB0 + (cur ^ 1) * 9216;
            const uint32_t vd = sb + VB0 + (cur ^ 1) * 9216;
            #pragma unroll
            for (int p = 0; p < 2; p++) {
                int idx = p * 256 + t;
                int row = idx >> 3, c = idx & 7;
                CP_ASYNC16(kd + row * 144 + c * 16, ksrc + (size_t)row * 64 + c * 8);
                CP_ASYNC16(vd + row * 144 + ((c ^ (row >> 3)) * 16),
                           vsrc + (size_t)row * 4096 + c * 8);
            }
            CP_COMMIT();
        }

        // MMA1
        float sacc[8][4];
        #pragma unroll
        for (int n = 0; n < 8; n++)
            #pragma unroll
            for (int i = 0; i < 4; i++) sacc[n][i] = 0.f;
        #pragma unroll
        for (int ks = 0; ks < 4; ks++) {
            uint32_t a0, a1, a2, a3;
            ldsm4(a0, a1, a2, a3, aQ + ks * 32);
            #pragma unroll
            for (int ntp = 0; ntp < 4; ntp++) {
                uint32_t b0, b1, b2, b3;
                ldsm4(b0, b1, b2, b3, kbase + kRow[ntp] + ks * 32);
                mma_bf16(sacc[2 * ntp    ], a0, a1, a2, a3, b0, b1);
                mma_bf16(sacc[2 * ntp + 1], a0, a1, a2, a3, b2, b3);
            }
        }

        // softmax in registers
        #pragma unroll
        for (int nt = 0; nt < 8; nt++) {
            float e0 = __expf(sacc[nt][0]);
            float e1 = __expf(sacc[nt][1]);
            float e2 = __expf(sacc[nt][2]);
            float e3 = __expf(sacc[nt][3]);
            lsum0 += e0 + e1;
            lsum1 += e2 + e3;
            sacc[nt][0] = e0; sacc[nt][1] = e1; sacc[nt][2] = e2; sacc[nt][3] = e3;
        }

        // MMA2
        #pragma unroll
        for (int ks = 0; ks < 4; ks++) {
            uint32_t a0 = pkbf(sacc[2*ks    ][0], sacc[2*ks    ][1]);
            uint32_t a1 = pkbf(sacc[2*ks    ][2], sacc[2*ks    ][3]);
            uint32_t a2 = pkbf(sacc[2*ks + 1][0], sacc[2*ks + 1][1]);
            uint32_t a3 = pkbf(sacc[2*ks + 1][2], sacc[2*ks + 1][3]);
            #pragma unroll
            for (int ntp = 0; ntp < 4; ntp++) {
                uint32_t xr = (uint32_t)(((2 * ks + lh) ^ (2 * ntp + lq)) << 4);
                uint32_t b0, b1, b2, b3;
                ldsm4(b0, b1, b2, b3, vbase + vRow[ntp] + xr);
                mma_bf16(oacc[2 * ntp    ], a0, a1, a2, a3, b0, b1);
                mma_bf16(oacc[2 * ntp + 1], a0, a1, a2, a3, b2, b3);
            }
        }

        if (kt < 63) CP_WAIT0();
        __syncthreads();
    }

    // epilogue: normalize + tf32-round ctx
    lsum0 += __shfl_xor_sync(0xffffffffu, lsum0, 1);
    lsum0 += __shfl_xor_sync(0xffffffffu, lsum0, 2);
    lsum1 += __shfl_xor_sync(0xffffffffu, lsum1, 1);
    lsum1 += __shfl_xor_sync(0xffffffffu, lsum1, 2);
    float inv0 = 1.0f / lsum0, inv1 = 1.0f / lsum1;

    const size_t obase = (size_t)(bh >> 3) * S_ * D_ + (size_t)(bh & 7) * HD_;
    uint32_t* op = (uint32_t*)(Oc + obase + (size_t)(qt * 128 + w * 16) * D_);
    #pragma unroll
    for (int nt = 0; nt < 8; nt++) {
        int col = nt * 8 + 2 * tig;
        *(uint2*)(op + (size_t)g       * D_ + col) =
            make_uint2(f2tf(oacc[nt][0] * inv0), f2tf(oacc[nt][1] * inv0));
        *(uint2*)(op + (size_t)(g + 8) * D_ + col) =
            make_uint2(f2tf(oacc[nt][2] * inv1), f2tf(oacc[nt][3] * inv1));
    }
}

// ---------------- launch ----------------
extern "C" void kernel_launch(void* const* d_in, const int* in_sizes, int n_in,
                              void* d_out, int out_size)
{
    (void)in_sizes; (void)n_in; (void)out_size;
    const float* x   = (const float*)d_in[0];
    const float* eps = (const float*)d_in[1];
    const float* wq  = (const float*)d_in[2];
    const float* bq  = (const float*)d_in[3];
    const float* wk  = (const float*)d_in[4];
    const float* bk  = (const float*)d_in[5];
    const float* wv  = (const float*)d_in[6];
    const float* bv  = (const float*)d_in[7];
    const float* wo  = (const float*)d_in[8];
    const float* bo  = (const float*)d_in[9];
    const float* we1 = (const float*)d_in[10];
    const float* be1 = (const float*)d_in[11];
    const float* we2 = (const float*)d_in[12];
    const float* be2 = (const float*)d_in[13];
    const float* wmu = (const float*)d_in[14];
    const float* bmu = (const float*)d_in[15];
    const float* wlv = (const float*)d_in[16];
    const float* blv = (const float*)d_in[17];
    const float* wf  = (const float*)d_in[18];
    const float* bf  = (const float*)d_in[19];
    float* out = (float*)d_out;

    float *p_xm, *p_lp, *p_xi, *p_wi, *p_ctx;
    uint16_t *p_qb, *p_kb, *p_vt;
    cudaGetSymbolAddress((void**)&p_xm,  g_xm_part);
    cudaGetSymbolAddress((void**)&p_lp,  g_lp);
    cudaGetSymbolAddress((void**)&p_xi,  g_xi);
    cudaGetSymbolAddress((void**)&p_wi,  g_wi);
    cudaGetSymbolAddress((void**)&p_qb,  g_qb);
    cudaGetSymbolAddress((void**)&p_kb,  g_kb);
    cudaGetSymbolAddress((void**)&p_vt,  g_vt);
    cudaGetSymbolAddress((void**)&p_ctx, g_ctx);

    cudaFuncSetAttribute(attn_mma_kernel,
                         cudaFuncAttributeMaxDynamicSharedMemorySize, ATT_SMEM_BYTES);
    cudaFuncSetAttribute(proj_mma_kernel,
                         cudaFuncAttributeMaxDynamicSharedMemorySize, PROJ_SMEM_BYTES);

    // fused pre-conversion pass (x + 4 weight matrices)
    cvt_all_kernel<<<4096 + 1024, 256>>>(x, wv, wq, wk, wo, p_xi, p_wi);

    mean_part_kernel<<<dim3(4, 8), 256>>>(x, p_xm);
    vae_kernel<<<1, 256>>>(p_xm, eps, we1, be1, we2, be2, wmu, bmu,
                           wlv, blv, wf, bf, p_lp, out + OUT_MAIN);

    dim3 pgrid(8, 64);
    proj_mma_kernel<<<pgrid, 256, PROJ_SMEM_BYTES>>>(p_xi, p_wi,           bv, p_lp, p_vt, 3);
    proj_mma_kernel<<<pgrid, 256, PROJ_SMEM_BYTES>>>(p_xi, p_wi + 1*D_*D_, bq, p_lp, p_qb, 1);
    proj_mma_kernel<<<pgrid, 256, PROJ_SMEM_BYTES>>>(p_xi, p_wi + 2*D_*D_, bk, p_lp, p_kb, 2);

    attn_mma_kernel<<<dim3(32, 16), 256, ATT_SMEM_BYTES>>>(p_qb, p_kb, p_vt, p_ctx);

    proj_mma_kernel<<<pgrid, 256, PROJ_SMEM_BYTES>>>(p_ctx, p_wi + 3*D_*D_, bo, p_lp, out, 0);
}